// round 4
// baseline (speedup 1.0000x reference)
#include <cuda_runtime.h>
#include <cuda_fp16.h>
#include <cstdint>

// ---------------------------------------------------------------------------
// StarBlock fused quantized MLP — int8 + fp16 dual-plane mma.sync (sm_103)
//
//  x = q/64 + r ;  q int8 (exact s8 GEMM, folded f32), r fp16 residual GEMM
//  s1,s2 -> exact integer floor-quant epilogue -> h int8
//  down: pure s8 GEMM (bit-exact), out = relu(acc/16384 + bdq)
// ---------------------------------------------------------------------------

#define B_ROWS 32768
#define DIN    1024
#define DHID   2048
#define DOUT   1024

#define C1_FOLD 1.220703125e-4f   // (1/64)*(1/128)
#define CDN     6.103515625e-5f   // 1/16384

// ------------------------- scratch (device globals) ------------------------
__device__ int8_t g_q  [(size_t)B_ROWS * DIN];       // 32 MiB
__device__ __half g_r  [(size_t)B_ROWS * DIN];       // 64 MiB
__device__ int8_t g_wB1[(size_t)(2 * DHID) * DIN];   // 4 MiB  [w1|w2 64-blocks]
__device__ __half g_wB2[(size_t)(2 * DHID) * DIN];   // 8 MiB
__device__ int8_t g_wdq[(size_t)DOUT * DOUT];        // 1 MiB
__device__ int8_t g_h  [(size_t)B_ROWS * DOUT];      // 32 MiB
__device__ float  g_b1[DHID], g_b2[DHID], g_bd[DOUT];

// ------------------------------- helpers -----------------------------------
__device__ __forceinline__ uint32_t smem_u32(const void* p) {
    uint32_t a;
    asm("{ .reg .u64 t; cvta.to.shared.u64 t, %1; cvt.u32.u64 %0, t; }"
        : "=r"(a) : "l"(p));
    return a;
}
__device__ __forceinline__ uint32_t sw64(uint32_t off) {
    return off ^ ((off >> 3) & 0x30);
}
__device__ __forceinline__ void cp16(uint32_t saddr, const void* gptr) {
    asm volatile("cp.async.cg.shared.global [%0], [%1], 16;"
                 :: "r"(saddr), "l"(gptr));
}
#define CP_COMMIT() asm volatile("cp.async.commit_group;" ::: "memory")
#define CP_WAIT(n)  asm volatile("cp.async.wait_group %0;" :: "n"(n) : "memory")

__device__ __forceinline__ void ldsm4(uint32_t* r, uint32_t addr) {
    asm volatile("ldmatrix.sync.aligned.m8n8.x4.shared.b16 {%0,%1,%2,%3}, [%4];"
                 : "=r"(r[0]), "=r"(r[1]), "=r"(r[2]), "=r"(r[3])
                 : "r"(addr));
}
__device__ __forceinline__ void mma_s8(int* d, const uint32_t* a,
                                       uint32_t b0, uint32_t b1) {
    asm volatile(
        "mma.sync.aligned.m16n8k32.row.col.s32.s8.s8.s32 "
        "{%0,%1,%2,%3},{%4,%5,%6,%7},{%8,%9},{%0,%1,%2,%3};"
        : "+r"(d[0]), "+r"(d[1]), "+r"(d[2]), "+r"(d[3])
        : "r"(a[0]), "r"(a[1]), "r"(a[2]), "r"(a[3]), "r"(b0), "r"(b1));
}
__device__ __forceinline__ void mma_f16(float* c, const uint32_t* a,
                                        uint32_t b0, uint32_t b1) {
    asm volatile(
        "mma.sync.aligned.m16n8k16.row.col.f32.f16.f16.f32 "
        "{%0,%1,%2,%3},{%4,%5,%6,%7},{%8,%9},{%0,%1,%2,%3};"
        : "+f"(c[0]), "+f"(c[1]), "+f"(c[2]), "+f"(c[3])
        : "r"(a[0]), "r"(a[1]), "r"(a[2]), "r"(a[3]), "r"(b0), "r"(b1));
}

// exact reproduction of reference floor-quant pipeline -> int8 h
__device__ __forceinline__ int8_t make_h8(float s1a, float s1b,
                                          float s2a, float s2b) {
    int a0 = (int)floorf(fminf(fmaxf(s1a, 0.f) * 128.f, 127.f));
    int a1 = (int)floorf(fminf(fmaxf(s1b, 0.f) * 128.f, 127.f));
    int q0 = (int)floorf(fminf(fmaxf(s2a * 128.f, -128.f), 127.f));
    int q1 = (int)floorf(fminf(fmaxf(s2b * 128.f, -128.f), 127.f));
    int t  = a0 * q0 + a1 * q1;
    int hq = t >> 7;
    hq = hq < -128 ? -128 : (hq > 127 ? 127 : hq);
    return (int8_t)hq;
}

// ------------------------------ prep kernels -------------------------------
__global__ void prep_weights_kernel(const float* __restrict__ w1,
                                    const float* __restrict__ w2,
                                    const float* __restrict__ wd,
                                    const float* __restrict__ b1,
                                    const float* __restrict__ b2,
                                    const float* __restrict__ bd) {
    int i = blockIdx.x * blockDim.x + threadIdx.x;
    if (i < DHID * DIN) {
        int r = i >> 10, c = i & 1023;
        int k1 = (int)rintf(fminf(fmaxf(w1[i] * 128.f, -128.f), 127.f));
        int k2 = (int)rintf(fminf(fmaxf(w2[i] * 128.f, -128.f), 127.f));
        int nb = r >> 6, rl = r & 63;
        size_t row1 = (size_t)nb * 128 + rl;       // w1 sub-block
        size_t row2 = row1 + 64;                   // w2 sub-block
        g_wB1[row1 * DIN + c] = (int8_t)k1;
        g_wB1[row2 * DIN + c] = (int8_t)k2;
        g_wB2[row1 * DIN + c] = __float2half_rn((float)k1 * 0.0078125f);
        g_wB2[row2 * DIN + c] = __float2half_rn((float)k2 * 0.0078125f);
    }
    if (i < DOUT * DOUT) {
        g_wdq[i] = (int8_t)(int)rintf(fminf(fmaxf(wd[i] * 128.f, -128.f), 127.f));
    }
    if (i < DHID) {
        g_b1[i] = rintf(b1[i] * 16384.f) * (1.f / 16384.f);
        g_b2[i] = rintf(b2[i] * 16384.f) * (1.f / 16384.f);
    }
    if (i < DOUT) {
        g_bd[i] = rintf(bd[i] * 16384.f) * (1.f / 16384.f);
    }
}

__global__ void split_x_kernel(const float* __restrict__ x) {
    size_t i = ((size_t)blockIdx.x * blockDim.x + threadIdx.x) * 4;
    float4 v = *(const float4*)(x + i);
    float f[4] = {v.x, v.y, v.z, v.w};
    uint32_t qpack = 0;
    __align__(8) __half rr[4];
#pragma unroll
    for (int k = 0; k < 4; k++) {
        int q = (int)rintf(f[k] * 64.f);
        q = q < -127 ? -127 : (q > 127 ? 127 : q);
        qpack |= ((uint32_t)(uint8_t)(int8_t)q) << (k * 8);
        rr[k] = __float2half_rn(f[k] - (float)q * 0.015625f);
    }
    *(uint32_t*)(&g_q[i]) = qpack;
    *(uint2*)(&g_r[i])    = *(uint2*)rr;
}

// ------------------------------ up GEMM ------------------------------------
// grid (32, 256). CTA tile: M=128 x (64 w1-units co-located with 64 w2-units).
// K=1024, BK=64, 3-stage cp.async. 8 warps: wm=wid&3 (32 rows), wn=wid>>2
// (32 of the 64 units). Stage (sw64 rows): A1 8K | A2 16K | B1 8K | B2 16K.
#define UP_A2  8192
#define UP_B1  24576
#define UP_B2  32768
#define UP_STG 49152
#define UP_HDR 1024
#define UP_SMEM (UP_HDR + 3 * UP_STG)

__device__ __forceinline__ void up_load(uint32_t st, int m0, int nb, int k0,
                                        int tid) {
#pragma unroll
    for (int j = 0; j < 2; j++) {                  // A1: 128r x 64B
        int id = tid + j * 256;
        int r = id >> 2, c = id & 3;
        cp16(st + sw64(r * 64 + c * 16),
             &g_q[(size_t)(m0 + r) * DIN + k0 + c * 16]);
    }
#pragma unroll
    for (int j = 0; j < 4; j++) {                  // A2: 128r x 2 subrows
        int id = tid + j * 256;
        int r = id >> 3, h = (id >> 2) & 1, c = id & 3;
        cp16(st + UP_A2 + sw64((r * 2 + h) * 64 + c * 16),
             &g_r[(size_t)(m0 + r) * DIN + k0 + h * 32 + c * 8]);
    }
#pragma unroll
    for (int j = 0; j < 2; j++) {                  // B1: 128r x 64B
        int id = tid + j * 256;
        int r = id >> 2, c = id & 3;
        cp16(st + UP_B1 + sw64(r * 64 + c * 16),
             &g_wB1[(size_t)(nb * 128 + r) * DIN + k0 + c * 16]);
    }
#pragma unroll
    for (int j = 0; j < 4; j++) {                  // B2: 128r x 2 subrows
        int id = tid + j * 256;
        int r = id >> 3, h = (id >> 2) & 1, c = id & 3;
        cp16(st + UP_B2 + sw64((r * 2 + h) * 64 + c * 16),
             &g_wB2[(size_t)(nb * 128 + r) * DIN + k0 + h * 32 + c * 8]);
    }
    CP_COMMIT();
}

__global__ void __launch_bounds__(256, 1) up_gemm_kernel() {
    extern __shared__ char smem[];
    const uint32_t sb = smem_u32(smem);
    const int tid  = threadIdx.x;
    const int lane = tid & 31;
    const int wm   = (tid >> 5) & 3;
    const int wn   = tid >> 7;            // 0..1
    const int m0   = blockIdx.y * 128;
    const int nb   = blockIdx.x;          // 0..31

    if (tid < 64) {
        ((float*)smem)[tid]      = g_b1[nb * 64 + tid];
        ((float*)smem)[64 + tid] = g_b2[nb * 64 + tid];
    }

    float acc1[2][4][4], acc2[2][4][4];
#pragma unroll
    for (int a = 0; a < 2; a++)
#pragma unroll
        for (int b = 0; b < 4; b++)
#pragma unroll
            for (int c = 0; c < 4; c++) { acc1[a][b][c] = 0.f; acc2[a][b][c] = 0.f; }

    const int lrow = lane & 15;
    const int lhalf = (lane >> 4) * 16;
    const int arow = wm * 32;

#pragma unroll
    for (int s = 0; s < 3; s++)
        up_load(sb + UP_HDR + s * UP_STG, m0, nb, s * 64, tid);

    for (int it = 0; it < 16; ++it) {
        const int rem = 15 - it;
        if (rem >= 2)      CP_WAIT(2);
        else if (rem == 1) CP_WAIT(1);
        else               CP_WAIT(0);
        __syncthreads();
        const uint32_t st = sb + UP_HDR + (it % 3) * UP_STG;

        // ---- plane 1: int8 (k=32 per mma), folded into f32 ----
#pragma unroll
        for (int ks = 0; ks < 2; ++ks) {
            const uint32_t abyte = ks * 32 + lhalf;
            uint32_t af[2][4];
#pragma unroll
            for (int mt = 0; mt < 2; ++mt)
                ldsm4(af[mt], st + sw64((arow + mt * 16 + lrow) * 64 + abyte));
            uint32_t b1f[2][4], b2f[2][4];
#pragma unroll
            for (int np = 0; np < 2; ++np) {
                int r1 = wn * 32 + np * 16 + lrow;
                ldsm4(b1f[np], st + UP_B1 + sw64(r1 * 64 + abyte));
                ldsm4(b2f[np], st + UP_B1 + sw64((r1 + 64) * 64 + abyte));
            }
#pragma unroll
            for (int mt = 0; mt < 2; ++mt)
#pragma unroll
                for (int np = 0; np < 2; ++np)
#pragma unroll
                    for (int sub = 0; sub < 2; ++sub) {
                        const int nt = np * 2 + sub;
                        int d[4] = {0, 0, 0, 0};
                        mma_s8(d, af[mt], b1f[np][sub], b1f[np][sub + 2]);
                        float* a1 = acc1[mt][nt];
                        a1[0] = fmaf((float)d[0], C1_FOLD, a1[0]);
                        a1[1] = fmaf((float)d[1], C1_FOLD, a1[1]);
                        a1[2] = fmaf((float)d[2], C1_FOLD, a1[2]);
                        a1[3] = fmaf((float)d[3], C1_FOLD, a1[3]);
                        int e[4] = {0, 0, 0, 0};
                        mma_s8(e, af[mt], b2f[np][sub], b2f[np][sub + 2]);
                        float* a2 = acc2[mt][nt];
                        a2[0] = fmaf((float)e[0], C1_FOLD, a2[0]);
                        a2[1] = fmaf((float)e[1], C1_FOLD, a2[1]);
                        a2[2] = fmaf((float)e[2], C1_FOLD, a2[2]);
                        a2[3] = fmaf((float)e[3], C1_FOLD, a2[3]);
                    }
        }

        // ---- plane 2: fp16 residual (k=16 per mma) ----
#pragma unroll
        for (int fs = 0; fs < 4; ++fs) {
            const int h = fs >> 1;
            const uint32_t fbyte = (fs & 1) * 32 + lhalf;
            uint32_t af[2][4];
#pragma unroll
            for (int mt = 0; mt < 2; ++mt)
                ldsm4(af[mt], st + UP_A2 +
                      sw64(((arow + mt * 16 + lrow) * 2 + h) * 64 + fbyte));
            uint32_t b1f[2][4], b2f[2][4];
#pragma unroll
            for (int np = 0; np < 2; ++np) {
                int r1 = wn * 32 + np * 16 + lrow;
                ldsm4(b1f[np], st + UP_B2 + sw64((r1 * 2 + h) * 64 + fbyte));
                ldsm4(b2f[np], st + UP_B2 + sw64(((r1 + 64) * 2 + h) * 64 + fbyte));
            }
#pragma unroll
            for (int mt = 0; mt < 2; ++mt)
#pragma unroll
                for (int np = 0; np < 2; ++np)
#pragma unroll
                    for (int sub = 0; sub < 2; ++sub) {
                        const int nt = np * 2 + sub;
                        mma_f16(acc1[mt][nt], af[mt], b1f[np][sub], b1f[np][sub + 2]);
                        mma_f16(acc2[mt][nt], af[mt], b2f[np][sub], b2f[np][sub + 2]);
                    }
        }

        __syncthreads();
        if (it + 3 < 16)
            up_load(st, m0, nb, (it + 3) * 64, tid);
    }
    __syncthreads();   // all reads of stage 0 done before reuse

    // ---- epilogue: exact integer h, staged through smem (128 x 32 int8) ----
    const float* sb1 = (const float*)smem;
    const float* sb2 = (const float*)smem + 64;
    char* s_h = smem + UP_HDR;
    const int g = lane >> 2, t = lane & 3;
#pragma unroll
    for (int mt = 0; mt < 2; ++mt) {
#pragma unroll
        for (int nt = 0; nt < 4; ++nt) {
            const int nloc = wn * 32 + nt * 8 + 2 * t;
            const int hc   = (nloc >> 1);
            const int r0   = wm * 32 + mt * 16 + g;
            const float b1a = sb1[nloc], b1b = sb1[nloc + 1];
            const float b2a = sb2[nloc], b2b = sb2[nloc + 1];
            const float* a1 = acc1[mt][nt];
            const float* a2 = acc2[mt][nt];
            s_h[r0 * 32 + hc] =
                make_h8(a1[0] + b1a, a1[1] + b1b, a2[0] + b2a, a2[1] + b2b);
            s_h[(r0 + 8) * 32 + hc] =
                make_h8(a1[2] + b1a, a1[3] + b1b, a2[2] + b2a, a2[3] + b2b);
        }
    }
    __syncthreads();
    {
        const int r = tid >> 1, half = tid & 1;
        uint4 v = *(uint4*)(s_h + r * 32 + half * 16);
        *(uint4*)(&g_h[(size_t)(m0 + r) * DOUT + nb * 32 + half * 16]) = v;
    }
}

// ------------------------------ down GEMM (int8, bit-exact) ----------------
// grid (16, 256). CTA M=128 x N=64, K=1024, BK=64, 3-stage.
// Stage: A 8K | B 4K = 12K.
#define DN_B   8192
#define DN_STG 12288
#define DN_HDR 1024
#define DN_SMEM (DN_HDR + 3 * DN_STG)

__device__ __forceinline__ void dn_load(uint32_t st, int m0, int n0, int k0,
                                        int tid) {
#pragma unroll
    for (int j = 0; j < 2; j++) {                  // A: 128r x 64B
        int id = tid + j * 256;
        int r = id >> 2, c = id & 3;
        cp16(st + sw64(r * 64 + c * 16),
             &g_h[(size_t)(m0 + r) * DOUT + k0 + c * 16]);
    }
    {
        int r = tid >> 2, c = tid & 3;             // B: 64r x 64B
        if (r < 64)
            cp16(st + DN_B + sw64(r * 64 + c * 16),
                 &g_wdq[(size_t)(n0 + r) * DOUT + k0 + c * 16]);
    }
    CP_COMMIT();
}

__global__ void __launch_bounds__(256, 1) down_gemm_kernel(float* __restrict__ out) {
    extern __shared__ char smem[];
    const uint32_t sb = smem_u32(smem);
    const int tid  = threadIdx.x;
    const int lane = tid & 31;
    const int wm   = (tid >> 5) & 3;
    const int wn   = tid >> 7;
    const int m0   = blockIdx.y * 128;
    const int n0   = blockIdx.x * 64;

    if (tid < 64) ((float*)smem)[tid] = g_bd[n0 + tid];

    int acc[2][4][4];
#pragma unroll
    for (int a = 0; a < 2; a++)
#pragma unroll
        for (int b = 0; b < 4; b++)
#pragma unroll
            for (int c = 0; c < 4; c++) acc[a][b][c] = 0;

    const int lrow = lane & 15;
    const int lhalf = (lane >> 4) * 16;
    const int arow = wm * 32;

#pragma unroll
    for (int s = 0; s < 3; s++)
        dn_load(sb + DN_HDR + s * DN_STG, m0, n0, s * 64, tid);

    for (int it = 0; it < 16; ++it) {
        const int rem = 15 - it;
        if (rem >= 2)      CP_WAIT(2);
        else if (rem == 1) CP_WAIT(1);
        else               CP_WAIT(0);
        __syncthreads();
        const uint32_t st = sb + DN_HDR + (it % 3) * DN_STG;

#pragma unroll
        for (int ks = 0; ks < 2; ++ks) {
            const uint32_t abyte = ks * 32 + lhalf;
            uint32_t af[2][4];
#pragma unroll
            for (int mt = 0; mt < 2; ++mt)
                ldsm4(af[mt], st + sw64((arow + mt * 16 + lrow) * 64 + abyte));
            uint32_t bf[2][4];
#pragma unroll
            for (int np = 0; np < 2; ++np)
                ldsm4(bf[np], st + DN_B +
                      sw64((wn * 32 + np * 16 + lrow) * 64 + abyte));
#pragma unroll
            for (int mt = 0; mt < 2; ++mt)
#pragma unroll
                for (int np = 0; np < 2; ++np)
#pragma unroll
                    for (int sub = 0; sub < 2; ++sub)
                        mma_s8(acc[mt][np * 2 + sub], af[mt],
                               bf[np][sub], bf[np][sub + 2]);
        }
        __syncthreads();
        if (it + 3 < 16)
            dn_load(st, m0, n0, (it + 3) * 64, tid);
    }

    const float* sbd = (const float*)smem;
    const int g = lane >> 2, t = lane & 3;
#pragma unroll
    for (int mt = 0; mt < 2; ++mt) {
#pragma unroll
        for (int nt = 0; nt < 4; ++nt) {
            const int nloc = wn * 32 + nt * 8 + 2 * t;
            const int r0 = m0 + wm * 32 + mt * 16 + g;
            const float bda = sbd[nloc], bdb = sbd[nloc + 1];
            const int* a = acc[mt][nt];
            float2 v0 = { fmaxf((float)a[0] * CDN + bda, 0.f),
                          fmaxf((float)a[1] * CDN + bdb, 0.f) };
            float2 v1 = { fmaxf((float)a[2] * CDN + bda, 0.f),
                          fmaxf((float)a[3] * CDN + bdb, 0.f) };
            *(float2*)(out + (size_t)r0 * DOUT + n0 + nloc)       = v0;
            *(float2*)(out + (size_t)(r0 + 8) * DOUT + n0 + nloc) = v1;
        }
    }
}

// ------------------------------- launch -------------------------------------
extern "C" void kernel_launch(void* const* d_in, const int* in_sizes, int n_in,
                              void* d_out, int out_size) {
    (void)in_sizes; (void)n_in; (void)out_size;
    const float* x  = (const float*)d_in[0];
    const float* w1 = (const float*)d_in[1];
    const float* b1 = (const float*)d_in[2];
    const float* w2 = (const float*)d_in[3];
    const float* b2 = (const float*)d_in[4];
    const float* wd = (const float*)d_in[5];
    const float* bd = (const float*)d_in[6];
    float* out = (float*)d_out;

    cudaFuncSetAttribute(up_gemm_kernel,
                         cudaFuncAttributeMaxDynamicSharedMemorySize, UP_SMEM);
    cudaFuncSetAttribute(down_gemm_kernel,
                         cudaFuncAttributeMaxDynamicSharedMemorySize, DN_SMEM);

    prep_weights_kernel<<<(DHID * DIN) / 256, 256>>>(w1, w2, wd, b1, b2, bd);
    split_x_kernel<<<(B_ROWS * DIN / 4) / 256, 256>>>(x);

    dim3 gup(DHID / 64, B_ROWS / 128);     // (32, 256)
    up_gemm_kernel<<<gup, 256, UP_SMEM>>>();

    dim3 gdn(DOUT / 64, B_ROWS / 128);     // (16, 256)
    down_gemm_kernel<<<gdn, 256, DN_SMEM>>>(out);
}

// round 5
// speedup vs baseline: 2.1700x; 2.1700x over previous
#include <cuda_runtime.h>
#include <cuda_bf16.h>
#include <cstdint>

// ---------------------------------------------------------------------------
// StarBlock fused quantized MLP — bf16 hi/lo dual-plane mma.sync, optimized
// schedule (BK=64, 3-stage cp.async ring, 1 barrier/iter, 512-thread CTAs).
// Numerics identical to the validated R1 kernel (rel_err 3.7e-4).
// ---------------------------------------------------------------------------

#define B_ROWS 32768
#define DIN    1024
#define DHID   2048
#define DOUT   1024
#define KSPLIT 2048            // hi | lo bf16 planes

// ------------------------- scratch (device globals) ------------------------
__device__ __nv_bfloat16 g_X [(size_t)B_ROWS * KSPLIT];     // 128 MiB [hi|lo]
__device__ __nv_bfloat16 g_wB[(size_t)(2 * DHID) * KSPLIT]; // 16 MiB, 256-row blocks
__device__ __nv_bfloat16 g_wd[(size_t)DOUT * DOUT];         // 2 MiB
__device__ __nv_bfloat16 g_h [(size_t)B_ROWS * DOUT];       // 64 MiB
__device__ float g_b1[DHID], g_b2[DHID], g_bd[DOUT];

// ------------------------------- helpers -----------------------------------
__device__ __forceinline__ uint32_t smem_u32(const void* p) {
    uint32_t a;
    asm("{ .reg .u64 t; cvta.to.shared.u64 t, %1; cvt.u32.u64 %0, t; }"
        : "=r"(a) : "l"(p));
    return a;
}
__device__ __forceinline__ uint32_t sw128(uint32_t off) {
    return off ^ ((off >> 3) & 0x70);      // 128B-row swizzle
}
__device__ __forceinline__ void cp16(uint32_t saddr, const void* gptr) {
    asm volatile("cp.async.cg.shared.global [%0], [%1], 16;"
                 :: "r"(saddr), "l"(gptr));
}
#define CP_COMMIT() asm volatile("cp.async.commit_group;" ::: "memory")
#define CP_WAIT(n)  asm volatile("cp.async.wait_group %0;" :: "n"(n) : "memory")

__device__ __forceinline__ void ldsm4(uint32_t* r, uint32_t addr) {
    asm volatile("ldmatrix.sync.aligned.m8n8.x4.shared.b16 {%0,%1,%2,%3}, [%4];"
                 : "=r"(r[0]), "=r"(r[1]), "=r"(r[2]), "=r"(r[3])
                 : "r"(addr));
}
__device__ __forceinline__ void mma16816(float* c, const uint32_t* a,
                                         uint32_t b0, uint32_t b1) {
    asm volatile(
        "mma.sync.aligned.m16n8k16.row.col.f32.bf16.bf16.f32 "
        "{%0,%1,%2,%3},{%4,%5,%6,%7},{%8,%9},{%0,%1,%2,%3};"
        : "+f"(c[0]), "+f"(c[1]), "+f"(c[2]), "+f"(c[3])
        : "r"(a[0]), "r"(a[1]), "r"(a[2]), "r"(a[3]), "r"(b0), "r"(b1));
}

// exact reproduction of reference floor-quant pipeline
__device__ __forceinline__ __nv_bfloat16 make_h(float s1a, float s1b,
                                                float s2a, float s2b) {
    int a0 = (int)floorf(fminf(fmaxf(s1a, 0.f) * 128.f, 127.f));
    int a1 = (int)floorf(fminf(fmaxf(s1b, 0.f) * 128.f, 127.f));
    int q0 = (int)floorf(fminf(fmaxf(s2a * 128.f, -128.f), 127.f));
    int q1 = (int)floorf(fminf(fmaxf(s2b * 128.f, -128.f), 127.f));
    int t  = a0 * q0 + a1 * q1;
    int hq = t >> 7;
    hq = hq < -128 ? -128 : (hq > 127 ? 127 : hq);
    return __float2bfloat16((float)hq * 0.0078125f);
}

// ------------------------------ prep kernels -------------------------------
__global__ void prep_weights_kernel(const float* __restrict__ w1,
                                    const float* __restrict__ w2,
                                    const float* __restrict__ wd,
                                    const float* __restrict__ b1,
                                    const float* __restrict__ b2,
                                    const float* __restrict__ bd) {
    int i = blockIdx.x * blockDim.x + threadIdx.x;
    if (i < DHID * DIN) {
        int r = i >> 10, c = i & 1023;
        float q1 = rintf(fminf(fmaxf(w1[i] * 128.f, -128.f), 127.f)) * 0.0078125f;
        float q2 = rintf(fminf(fmaxf(w2[i] * 128.f, -128.f), 127.f)) * 0.0078125f;
        __nv_bfloat16 h1 = __float2bfloat16(q1);
        __nv_bfloat16 h2 = __float2bfloat16(q2);
        int nb = r >> 7, rl = r & 127;
        size_t row1 = (size_t)nb * 256 + rl;       // w1 rows of block
        size_t row2 = row1 + 128;                  // w2 rows of block
        g_wB[row1 * KSPLIT + c]       = h1;        // hi plane
        g_wB[row1 * KSPLIT + c + DIN] = h1;        // lo plane (same weights)
        g_wB[row2 * KSPLIT + c]       = h2;
        g_wB[row2 * KSPLIT + c + DIN] = h2;
    }
    if (i < DOUT * DOUT) {
        float qd = rintf(fminf(fmaxf(wd[i] * 128.f, -128.f), 127.f)) * 0.0078125f;
        g_wd[i] = __float2bfloat16(qd);
    }
    if (i < DHID) {
        g_b1[i] = rintf(b1[i] * 16384.f) * (1.f / 16384.f);
        g_b2[i] = rintf(b2[i] * 16384.f) * (1.f / 16384.f);
    }
    if (i < DOUT) {
        g_bd[i] = rintf(bd[i] * 16384.f) * (1.f / 16384.f);
    }
}

__global__ void split_x_kernel(const float* __restrict__ x) {
    size_t i = ((size_t)blockIdx.x * blockDim.x + threadIdx.x) * 4;
    float4 v = *(const float4*)(x + i);
    int r = (int)(i >> 10), c = (int)(i & 1023);
    __align__(8) __nv_bfloat16 hi[4], lo[4];
    float f[4] = {v.x, v.y, v.z, v.w};
#pragma unroll
    for (int k = 0; k < 4; k++) {
        hi[k] = __float2bfloat16(f[k]);
        lo[k] = __float2bfloat16(f[k] - __bfloat162float(hi[k]));
    }
    size_t base = (size_t)r * KSPLIT + c;
    *(uint2*)(&g_X[base])       = *(uint2*)hi;
    *(uint2*)(&g_X[base + DIN]) = *(uint2*)lo;
}

// ------------------------------ up GEMM ------------------------------------
// grid (16, 256), 512 threads. CTA: M=128 x 128 dhid-channels
// (B tile = 256 rows: 128 w1 + 128 w2). K=2048, BK=64, 3-stage ring.
// 16 warps: wm = wid&3 (32 rows), wn = wid>>2 (32 channels).
// Stage: A 128x128B (16K) @0 | B 256x128B (32K) @16384.  STG=48K.
#define UP_STG  49152
#define UP_HDR  1024
#define UP_SMEM (UP_HDR + 3 * UP_STG)
#define UP_NK   32

__device__ __forceinline__ void up_load(uint32_t st, int m0, int nb, int k0,
                                        int tid) {
#pragma unroll
    for (int j = 0; j < 2; j++) {                 // A: 1024 chunks
        int id = tid + j * 512;
        int r = id >> 3, c = id & 7;
        cp16(st + sw128(r * 128 + c * 16),
             &g_X[(size_t)(m0 + r) * KSPLIT + k0 + c * 8]);
    }
#pragma unroll
    for (int j = 0; j < 4; j++) {                 // B: 2048 chunks
        int id = tid + j * 512;
        int r = id >> 3, c = id & 7;
        cp16(st + 16384 + sw128(r * 128 + c * 16),
             &g_wB[((size_t)nb * 256 + r) * KSPLIT + k0 + c * 8]);
    }
    CP_COMMIT();
}

__global__ void __launch_bounds__(512, 1) up_gemm_kernel() {
    extern __shared__ char smem[];
    const uint32_t sb = smem_u32(smem);
    const int tid  = threadIdx.x;
    const int lane = tid & 31;
    const int wid  = tid >> 5;
    const int wm   = wid & 3;
    const int wn   = wid >> 2;
    const int m0   = blockIdx.y * 128;
    const int nb   = blockIdx.x;                  // 0..15

    if (tid < 128) {
        ((float*)smem)[tid]       = g_b1[nb * 128 + tid];
        ((float*)smem)[128 + tid] = g_b2[nb * 128 + tid];
    }

    float acc1[2][4][4], acc2[2][4][4];
#pragma unroll
    for (int a = 0; a < 2; a++)
#pragma unroll
        for (int b = 0; b < 4; b++)
#pragma unroll
            for (int c = 0; c < 4; c++) { acc1[a][b][c] = 0.f; acc2[a][b][c] = 0.f; }

    const int lrow  = lane & 15;
    const int lhalf = (lane >> 4) * 16;
    const int arow  = wm * 32;

    up_load(sb + UP_HDR + 0 * UP_STG, m0, nb, 0, tid);
    up_load(sb + UP_HDR + 1 * UP_STG, m0, nb, 64, tid);

    for (int it = 0; it < UP_NK; ++it) {
        if (it + 1 < UP_NK) { CP_WAIT(1); } else { CP_WAIT(0); }
        __syncthreads();
        // refill the slot consumed at iteration it-1 (all reads fenced above)
        if (it + 2 < UP_NK)
            up_load(sb + UP_HDR + ((it + 2) % 3) * UP_STG, m0, nb,
                    (it + 2) * 64, tid);

        const uint32_t stA = sb + UP_HDR + (it % 3) * UP_STG;
        const uint32_t stB = stA + 16384;

#pragma unroll
        for (int ks = 0; ks < 4; ++ks) {
            const uint32_t abyte = ks * 32 + lhalf;
            uint32_t af[2][4];
#pragma unroll
            for (int mt = 0; mt < 2; ++mt)
                ldsm4(af[mt], stA + sw128((arow + mt * 16 + lrow) * 128 + abyte));
            uint32_t b1f[2][4], b2f[2][4];
#pragma unroll
            for (int np = 0; np < 2; ++np) {
                const int r1 = wn * 32 + np * 16 + lrow;
                ldsm4(b1f[np], stB + sw128(r1 * 128 + abyte));
                ldsm4(b2f[np], stB + sw128((r1 + 128) * 128 + abyte));
            }
#pragma unroll
            for (int mt = 0; mt < 2; ++mt)
#pragma unroll
                for (int np = 0; np < 2; ++np)
#pragma unroll
                    for (int sub = 0; sub < 2; ++sub) {
                        const int nt = np * 2 + sub;
                        mma16816(acc1[mt][nt], af[mt], b1f[np][sub], b1f[np][sub + 2]);
                        mma16816(acc2[mt][nt], af[mt], b2f[np][sub], b2f[np][sub + 2]);
                    }
        }
    }
    __syncthreads();   // loop done; safe to reuse stage 0 as h staging

    // ---- epilogue: exact integer h, staged via smem (128 x 64 bf16) -------
    const float* sb1 = (const float*)smem;
    const float* sb2 = (const float*)smem + 128;
    __nv_bfloat16* s_h = (__nv_bfloat16*)(smem + UP_HDR);
    const int g = lane >> 2, t = lane & 3;
#pragma unroll
    for (int mt = 0; mt < 2; ++mt) {
#pragma unroll
        for (int nt = 0; nt < 4; ++nt) {
            const int nloc = wn * 32 + nt * 8 + 2 * t;
            const int hc   = nloc >> 1;
            const int r0   = wm * 32 + mt * 16 + g;
            const float b1a = sb1[nloc], b1b = sb1[nloc + 1];
            const float b2a = sb2[nloc], b2b = sb2[nloc + 1];
            const float* a1 = acc1[mt][nt];
            const float* a2 = acc2[mt][nt];
            s_h[r0 * 64 + hc] =
                make_h(a1[0] + b1a, a1[1] + b1b, a2[0] + b2a, a2[1] + b2b);
            s_h[(r0 + 8) * 64 + hc] =
                make_h(a1[2] + b1a, a1[3] + b1b, a2[2] + b2a, a2[3] + b2b);
        }
    }
    __syncthreads();
    {   // coalesced 16B stores: 128 rows x 128B = 1024 chunks
#pragma unroll
        for (int j = 0; j < 2; j++) {
            int id = tid + j * 512;
            int r = id >> 3, c = id & 7;
            uint4 v = *(uint4*)((char*)s_h + r * 128 + c * 16);
            *(uint4*)(&g_h[(size_t)(m0 + r) * DOUT + nb * 64 + c * 8]) = v;
        }
    }
}

// ------------------------------ down GEMM ----------------------------------
// grid (8, 256), 512 threads. CTA: M=128 x N=128, K=1024, BK=64, 3-stage.
// Stage: A 16K @0 | B 16K @16384.  STG=32K.
#define DN_STG  32768
#define DN_HDR  1024
#define DN_SMEM (DN_HDR + 3 * DN_STG)
#define DN_NK   16

__device__ __forceinline__ void dn_load(uint32_t st, int m0, int n0, int k0,
                                        int tid) {
#pragma unroll
    for (int j = 0; j < 2; j++) {                 // A: 1024 chunks
        int id = tid + j * 512;
        int r = id >> 3, c = id & 7;
        cp16(st + sw128(r * 128 + c * 16),
             &g_h[(size_t)(m0 + r) * DOUT + k0 + c * 8]);
    }
#pragma unroll
    for (int j = 0; j < 2; j++) {                 // B: 1024 chunks
        int id = tid + j * 512;
        int r = id >> 3, c = id & 7;
        cp16(st + 16384 + sw128(r * 128 + c * 16),
             &g_wd[(size_t)(n0 + r) * DOUT + k0 + c * 8]);
    }
    CP_COMMIT();
}

__global__ void __launch_bounds__(512, 1) down_gemm_kernel(float* __restrict__ out) {
    extern __shared__ char smem[];
    const uint32_t sb = smem_u32(smem);
    const int tid  = threadIdx.x;
    const int lane = tid & 31;
    const int wid  = tid >> 5;
    const int wm   = wid & 3;
    const int wn   = wid >> 2;
    const int m0   = blockIdx.y * 128;
    const int n0   = blockIdx.x * 128;

    if (tid < 128) ((float*)smem)[tid] = g_bd[n0 + tid];

    float acc[2][4][4];
#pragma unroll
    for (int a = 0; a < 2; a++)
#pragma unroll
        for (int b = 0; b < 4; b++)
#pragma unroll
            for (int c = 0; c < 4; c++) acc[a][b][c] = 0.f;

    const int lrow  = lane & 15;
    const int lhalf = (lane >> 4) * 16;
    const int arow  = wm * 32;

    dn_load(sb + DN_HDR + 0 * DN_STG, m0, n0, 0, tid);
    dn_load(sb + DN_HDR + 1 * DN_STG, m0, n0, 64, tid);

    for (int it = 0; it < DN_NK; ++it) {
        if (it + 1 < DN_NK) { CP_WAIT(1); } else { CP_WAIT(0); }
        __syncthreads();
        if (it + 2 < DN_NK)
            dn_load(sb + DN_HDR + ((it + 2) % 3) * DN_STG, m0, n0,
                    (it + 2) * 64, tid);

        const uint32_t stA = sb + DN_HDR + (it % 3) * DN_STG;
        const uint32_t stB = stA + 16384;

#pragma unroll
        for (int ks = 0; ks < 4; ++ks) {
            const uint32_t abyte = ks * 32 + lhalf;
            uint32_t af[2][4];
#pragma unroll
            for (int mt = 0; mt < 2; ++mt)
                ldsm4(af[mt], stA + sw128((arow + mt * 16 + lrow) * 128 + abyte));
            uint32_t bf[2][4];
#pragma unroll
            for (int np = 0; np < 2; ++np)
                ldsm4(bf[np], stB + sw128((wn * 32 + np * 16 + lrow) * 128 + abyte));
#pragma unroll
            for (int mt = 0; mt < 2; ++mt)
#pragma unroll
                for (int np = 0; np < 2; ++np)
#pragma unroll
                    for (int sub = 0; sub < 2; ++sub)
                        mma16816(acc[mt][np * 2 + sub], af[mt],
                                 bf[np][sub], bf[np][sub + 2]);
        }
    }

    const float* sbd = (const float*)smem;
    const int g = lane >> 2, t = lane & 3;
#pragma unroll
    for (int mt = 0; mt < 2; ++mt) {
#pragma unroll
        for (int nt = 0; nt < 4; ++nt) {
            const int nloc = wn * 32 + nt * 8 + 2 * t;
            const int r0 = m0 + wm * 32 + mt * 16 + g;
            const float bda = sbd[nloc], bdb = sbd[nloc + 1];
            const float* a = acc[mt][nt];
            float2 v0 = { fmaxf(a[0] + bda, 0.f), fmaxf(a[1] + bdb, 0.f) };
            float2 v1 = { fmaxf(a[2] + bda, 0.f), fmaxf(a[3] + bdb, 0.f) };
            *(float2*)(out + (size_t)r0 * DOUT + n0 + nloc)       = v0;
            *(float2*)(out + (size_t)(r0 + 8) * DOUT + n0 + nloc) = v1;
        }
    }
}

// ------------------------------- launch -------------------------------------
extern "C" void kernel_launch(void* const* d_in, const int* in_sizes, int n_in,
                              void* d_out, int out_size) {
    (void)in_sizes; (void)n_in; (void)out_size;
    const float* x  = (const float*)d_in[0];
    const float* w1 = (const float*)d_in[1];
    const float* b1 = (const float*)d_in[2];
    const float* w2 = (const float*)d_in[3];
    const float* b2 = (const float*)d_in[4];
    const float* wd = (const float*)d_in[5];
    const float* bd = (const float*)d_in[6];
    float* out = (float*)d_out;

    cudaFuncSetAttribute(up_gemm_kernel,
                         cudaFuncAttributeMaxDynamicSharedMemorySize, UP_SMEM);
    cudaFuncSetAttribute(down_gemm_kernel,
                         cudaFuncAttributeMaxDynamicSharedMemorySize, DN_SMEM);

    prep_weights_kernel<<<(DHID * DIN) / 256, 256>>>(w1, w2, wd, b1, b2, bd);
    split_x_kernel<<<(B_ROWS * DIN / 4) / 256, 256>>>(x);

    dim3 gup(DHID / 128, B_ROWS / 128);    // (16, 256)
    up_gemm_kernel<<<gup, 512, UP_SMEM>>>();

    dim3 gdn(DOUT / 128, B_ROWS / 128);    // (8, 256)
    down_gemm_kernel<<<gdn, 512, DN_SMEM>>>(out);
}